// round 13
// baseline (speedup 1.0000x reference)
#include <cuda_runtime.h>
#include <cfloat>

#define BATCH 4
#define NREF  8192
#define MQ    8192
#define KNN   16
#define WARPS_PER_BLOCK 8

// Packed ref points: x, y, z, |r|^2   (512 KB static scratch — allocation-free)
__device__ float4 g_packed[BATCH * NREF];

// Sum of squares, form h2s: z^2 rounded seeds the FMA, x^2 fused, y^2 rounded+added:
//   rn( fma(x,x, rn(z*z)) + rn(y*y) )
__device__ __forceinline__ float sumsq_h2s(float x, float y, float z) {
    return __fadd_rn(__fmaf_rn(x, x, __fmul_rn(z, z)), __fmul_rn(y, y));
}

// ---------------------------------------------------------------------------
// Pack kernel: compute r_sq once per ref point, store as float4.
// ---------------------------------------------------------------------------
__global__ void knn_pack_kernel(const float* __restrict__ ref) {
    int i = blockIdx.x * blockDim.x + threadIdx.x;
    if (i >= BATCH * NREF) return;
    float x = ref[i * 3 + 0];
    float y = ref[i * 3 + 1];
    float z = ref[i * 3 + 2];
    g_packed[i] = make_float4(x, y, z, sumsq_h2s(x, y, z));
}

// ---------------------------------------------------------------------------
// Main kernel: one warp per query.
// Warp-cooperative sorted top-16: lanes 0..15 each hold one slot (ascending).
// Rounding model:
//   cross = fma(q2,rz, fma(q1,ry, rn(q0*rx)))    (cublas ascending FMA chain)
//   sq    = rn( fma(x,x, rn(z*z)) + rn(y*y) )    (form h2s — this probe)
//   d2    = max((qsq + rsq) - 2*cross, 0)        (2*cross exact)
// Ties broken by lower index everywhere, matching lax.top_k stability.
// ---------------------------------------------------------------------------
__global__ void __launch_bounds__(WARPS_PER_BLOCK * 32)
knn_topk_kernel(const float* __restrict__ query,
                float* __restrict__ out_dist,
                float* __restrict__ out_idx) {
    const unsigned FULL = 0xFFFFFFFFu;
    const int warp = threadIdx.x >> 5;
    const int lane = threadIdx.x & 31;
    const int g = blockIdx.x * WARPS_PER_BLOCK + warp;   // global query id
    if (g >= BATCH * MQ) return;
    const int b = g >> 13;                               // g / 8192

    const float4* __restrict__ pref = &g_packed[b * NREF];

    // Query coords (broadcast load; all lanes same)
    const float q0 = __ldg(&query[g * 3 + 0]);
    const float q1 = __ldg(&query[g * 3 + 1]);
    const float q2 = __ldg(&query[g * 3 + 2]);
    const float qsq = sumsq_h2s(q0, q1, q2);

    // Sorted list, one slot per lane (lanes 0..15). FLT_MAX sentinels.
    float slotD = FLT_MAX;
    int   slotI = 0x7FFFFFFF;
    float kth = FLT_MAX;   // value of slot 15 (warp-uniform)

    #pragma unroll 4
    for (int j = 0; j < NREF / 32; ++j) {
        const int n = (j << 5) + lane;
        const float4 r = __ldg(&pref[n]);

        // cross: ascending FMA accumulation (acc starts at 0) — form b
        const float cross = __fmaf_rn(q2, r.z,
                             __fmaf_rn(q1, r.y,
                              __fmul_rn(q0, r.x)));
        // d2 = max((qsq + rsq) - 2*cross, 0)
        const float d2 = fmaxf(
            __fsub_rn(__fadd_rn(qsq, r.w), __fmul_rn(2.0f, cross)), 0.0f);

        unsigned bm = __ballot_sync(FULL, d2 < kth);
        while (bm) {
            const int s = __ffs(bm) - 1;
            bm &= bm - 1;
            const float nd = __shfl_sync(FULL, d2, s);   // warp-uniform
            if (!(nd < kth)) continue;                    // uniform branch
            const int ni = (j << 5) + s;

            // rank: slots with value <= nd stay in place (ties keep lower idx)
            const unsigned le =
                __ballot_sync(FULL, (lane < KNN) && (slotD <= nd));
            const int pos = __popc(le);                   // <= 15 (nd < kth)

            const float upD = __shfl_up_sync(FULL, slotD, 1);
            const int   upI = __shfl_up_sync(FULL, slotI, 1);
            if (lane < KNN) {
                if (lane == pos)      { slotD = nd;  slotI = ni;  }
                else if (lane > pos)  { slotD = upD; slotI = upI; }
            }
            kth = __shfl_sync(FULL, slotD, KNN - 1);
        }
    }

    if (lane < KNN) {
        out_dist[g * KNN + lane] = __fsqrt_rn(slotD);   // correctly-rounded sqrt
        out_idx [g * KNN + lane] = (float)slotI;        // indices as float32
    }
}

// ---------------------------------------------------------------------------
// kernel_launch: inputs per metadata order: ref [B,N,3] f32, query [B,M,3] f32,
// k (ignored; compile-time 16). Output: dist [B,M,16] f32 then idx [B,M,16].
// ---------------------------------------------------------------------------
extern "C" void kernel_launch(void* const* d_in, const int* in_sizes, int n_in,
                              void* d_out, int out_size) {
    const float* ref   = (const float*)d_in[0];
    const float* query = (const float*)d_in[1];
    float* out = (float*)d_out;

    knn_pack_kernel<<<(BATCH * NREF + 255) / 256, 256>>>(ref);

    const int nq = BATCH * MQ;
    knn_topk_kernel<<<nq / WARPS_PER_BLOCK, WARPS_PER_BLOCK * 32>>>(
        query, out, out + (size_t)nq * KNN);
}

// round 14
// speedup vs baseline: 1.0369x; 1.0369x over previous
#include <cuda_runtime.h>
#include <cfloat>

#define BATCH 4
#define NREF  8192
#define MQ    8192
#define KNN   16
#define WARPS_PER_BLOCK 8

// Packed ref points: x, y, z, |r|^2   (512 KB static scratch — allocation-free)
__device__ float4 g_packed[BATCH * NREF];

// Sum of squares, form h2s (bit-matches reference):
//   rn( fma(x,x, rn(z*z)) + rn(y*y) )
__device__ __forceinline__ float sumsq_h2s(float x, float y, float z) {
    return __fadd_rn(__fmaf_rn(x, x, __fmul_rn(z, z)), __fmul_rn(y, y));
}

// ---------------------------------------------------------------------------
// Pack kernel: compute r_sq once per ref point, store as float4.
// ---------------------------------------------------------------------------
__global__ void knn_pack_kernel(const float* __restrict__ ref) {
    int i = blockIdx.x * blockDim.x + threadIdx.x;
    if (i >= BATCH * NREF) return;
    float x = ref[i * 3 + 0];
    float y = ref[i * 3 + 1];
    float z = ref[i * 3 + 2];
    g_packed[i] = make_float4(x, y, z, sumsq_h2s(x, y, z));
}

// ---------------------------------------------------------------------------
// Main kernel: TWO queries per warp.
// Lanes 0..15  = sorted top-16 list of query A (pair*2)
// Lanes 16..31 = sorted top-16 list of query B (pair*2+1)
// Each iteration loads 32 candidates once, evaluates both queries.
// Rounding model (verified bit-exact vs reference in R13):
//   cross = fma(q2,rz, fma(q1,ry, rn(q0*rx)))
//   sq    = rn( fma(x,x, rn(z*z)) + rn(y*y) )
//   d2    = max((qsq + rsq) - 2*cross, 0)
// Ties broken by lower index everywhere (lax.top_k stability).
// ---------------------------------------------------------------------------
__global__ void __launch_bounds__(WARPS_PER_BLOCK * 32)
knn_topk_kernel(const float* __restrict__ query,
                float* __restrict__ out_dist,
                float* __restrict__ out_idx) {
    const unsigned FULL = 0xFFFFFFFFu;
    const int warp = threadIdx.x >> 5;
    const int lane = threadIdx.x & 31;
    const int pair = blockIdx.x * WARPS_PER_BLOCK + warp;   // 16384 pairs
    const int half = lane >> 4;         // 0 = query A, 1 = query B
    const int hl   = lane & 15;         // slot index within my half
    const int gmy  = (pair << 1) + half;                    // my half's query
    const int b    = gmy >> 13;         // batch (A,B always same batch)

    const float4* __restrict__ pref = &g_packed[b * NREF];

    // Each lane loads its half's query, then both halves' coords via shfl.
    const float mq0 = __ldg(&query[gmy * 3 + 0]);
    const float mq1 = __ldg(&query[gmy * 3 + 1]);
    const float mq2 = __ldg(&query[gmy * 3 + 2]);
    const float msq = sumsq_h2s(mq0, mq1, mq2);

    const float a0 = __shfl_sync(FULL, mq0, 0);
    const float a1 = __shfl_sync(FULL, mq1, 0);
    const float a2 = __shfl_sync(FULL, mq2, 0);
    const float asq = __shfl_sync(FULL, msq, 0);
    const float c0 = __shfl_sync(FULL, mq0, 16);
    const float c1 = __shfl_sync(FULL, mq1, 16);
    const float c2 = __shfl_sync(FULL, mq2, 16);
    const float csq = __shfl_sync(FULL, msq, 16);

    // Sorted list: one slot per lane, 16 per half. FLT_MAX sentinels.
    float slotD = FLT_MAX;
    int   slotI = 0x7FFFFFFF;
    float kthA = FLT_MAX;   // lane 15's value (query A threshold)
    float kthB = FLT_MAX;   // lane 31's value (query B threshold)

    #pragma unroll 4
    for (int j = 0; j < NREF / 32; ++j) {
        const float4 r = __ldg(&pref[(j << 5) + lane]);

        // Query A: cross (ascending FMA) + d2
        const float crA = __fmaf_rn(a2, r.z,
                           __fmaf_rn(a1, r.y, __fmul_rn(a0, r.x)));
        const float d2A = fmaxf(
            __fsub_rn(__fadd_rn(asq, r.w), __fmul_rn(2.0f, crA)), 0.0f);

        // Query B
        const float crB = __fmaf_rn(c2, r.z,
                           __fmaf_rn(c1, r.y, __fmul_rn(c0, r.x)));
        const float d2B = fmaxf(
            __fsub_rn(__fadd_rn(csq, r.w), __fmul_rn(2.0f, crB)), 0.0f);

        unsigned bmA = __ballot_sync(FULL, d2A < kthA);
        unsigned bmB = __ballot_sync(FULL, d2B < kthB);

        while (bmA) {
            const int s = __ffs(bmA) - 1;
            bmA &= bmA - 1;
            const float nd = __shfl_sync(FULL, d2A, s);  // warp-uniform
            if (!(nd < kthA)) continue;                   // uniform branch
            const int ni = (j << 5) + s;

            // rank within half 0: ties keep lower index (<=)
            const unsigned le =
                __ballot_sync(FULL, (half == 0) && (slotD <= nd));
            const int pos = __popc(le);                   // <= 15

            const float upD = __shfl_up_sync(FULL, slotD, 1);
            const int   upI = __shfl_up_sync(FULL, slotI, 1);
            if (half == 0) {
                if (hl == pos)      { slotD = nd;  slotI = ni;  }
                else if (hl > pos)  { slotD = upD; slotI = upI; }
            }
            kthA = __shfl_sync(FULL, slotD, 15);
        }

        while (bmB) {
            const int s = __ffs(bmB) - 1;
            bmB &= bmB - 1;
            const float nd = __shfl_sync(FULL, d2B, s);  // warp-uniform
            if (!(nd < kthB)) continue;                   // uniform branch
            const int ni = (j << 5) + s;

            // rank within half 1 (ballot bits 16..31 only)
            const unsigned le =
                __ballot_sync(FULL, (half == 1) && (slotD <= nd));
            const int pos = __popc(le);                   // <= 15

            const float upD = __shfl_up_sync(FULL, slotD, 1);
            const int   upI = __shfl_up_sync(FULL, slotI, 1);
            if (half == 1) {
                if (hl == pos)      { slotD = nd;  slotI = ni;  }
                else if (hl > pos)  { slotD = upD; slotI = upI; }
            }
            kthB = __shfl_sync(FULL, slotD, 31);
        }
    }

    // All 32 lanes write: each lane owns slot hl of its half's query.
    out_dist[gmy * KNN + hl] = __fsqrt_rn(slotD);
    out_idx [gmy * KNN + hl] = (float)slotI;
}

// ---------------------------------------------------------------------------
// kernel_launch: inputs per metadata order: ref [B,N,3] f32, query [B,M,3] f32,
// k (ignored; compile-time 16). Output: dist [B,M,16] f32 then idx [B,M,16].
// ---------------------------------------------------------------------------
extern "C" void kernel_launch(void* const* d_in, const int* in_sizes, int n_in,
                              void* d_out, int out_size) {
    const float* ref   = (const float*)d_in[0];
    const float* query = (const float*)d_in[1];
    float* out = (float*)d_out;

    knn_pack_kernel<<<(BATCH * NREF + 255) / 256, 256>>>(ref);

    const int nq = BATCH * MQ;                     // 32768 queries
    const int npairs = nq / 2;                     // 16384 warps
    knn_topk_kernel<<<npairs / WARPS_PER_BLOCK, WARPS_PER_BLOCK * 32>>>(
        query, out, out + (size_t)nq * KNN);
}

// round 15
// speedup vs baseline: 1.1015x; 1.0623x over previous
#include <cuda_runtime.h>
#include <cfloat>

#define BATCH 4
#define NREF  8192
#define MQ    8192
#define KNN   16
#define WARPS_PER_BLOCK 8

// Packed ref points: x, y, z, |r|^2   (512 KB static scratch — allocation-free)
__device__ float4 g_packed[BATCH * NREF];

// Sum of squares, form h2s (bit-matches reference):
//   rn( fma(x,x, rn(z*z)) + rn(y*y) )
__device__ __forceinline__ float sumsq_h2s(float x, float y, float z) {
    return __fadd_rn(__fmaf_rn(x, x, __fmul_rn(z, z)), __fmul_rn(y, y));
}

__global__ void knn_pack_kernel(const float* __restrict__ ref) {
    int i = blockIdx.x * blockDim.x + threadIdx.x;
    if (i >= BATCH * NREF) return;
    float x = ref[i * 3 + 0];
    float y = ref[i * 3 + 1];
    float z = ref[i * 3 + 2];
    g_packed[i] = make_float4(x, y, z, sumsq_h2s(x, y, z));
}

// raw d2 (unclamped): rn( (qsq+rsq) - 2*cross ) via fused fma(-2,cr,s).
// 2*cr is exact, so fma(-2,cr,s) == fsub(fadd(qsq,rsq), fmul(2,cr)) bitwise.
__device__ __forceinline__ float rawd2(float q0, float q1, float q2,
                                       float qsq, const float4& r) {
    const float cr = __fmaf_rn(q2, r.z, __fmaf_rn(q1, r.y, __fmul_rn(q0, r.x)));
    return __fmaf_rn(-2.0f, cr, __fadd_rn(qsq, r.w));
}

// ---------------------------------------------------------------------------
// Main kernel: TWO queries per warp, 64 candidates per iteration (ILP-2).
// Lanes 0..15 hold query A's sorted top-16; lanes 16..31 hold query B's.
// Filter on raw (unclamped) d2; clamp at insert. Inserts with rank 16 are
// structural no-ops, so no in-loop threshold recheck is needed.
// Ties broken by lower index everywhere (lax.top_k stability).
// ---------------------------------------------------------------------------
__global__ void __launch_bounds__(WARPS_PER_BLOCK * 32)
knn_topk_kernel(const float* __restrict__ query,
                float* __restrict__ out_dist,
                float* __restrict__ out_idx) {
    const unsigned FULL = 0xFFFFFFFFu;
    const int warp = threadIdx.x >> 5;
    const int lane = threadIdx.x & 31;
    const int pair = blockIdx.x * WARPS_PER_BLOCK + warp;
    const int half = lane >> 4;          // 0 = query A, 1 = query B
    const int hl   = lane & 15;          // slot index within my half
    const int gmy  = (pair << 1) + half;
    const int b    = gmy >> 13;

    const float4* __restrict__ pref = &g_packed[b * NREF];

    const float mq0 = __ldg(&query[gmy * 3 + 0]);
    const float mq1 = __ldg(&query[gmy * 3 + 1]);
    const float mq2 = __ldg(&query[gmy * 3 + 2]);
    const float msq = sumsq_h2s(mq0, mq1, mq2);

    const float a0 = __shfl_sync(FULL, mq0, 0);
    const float a1 = __shfl_sync(FULL, mq1, 0);
    const float a2 = __shfl_sync(FULL, mq2, 0);
    const float asq = __shfl_sync(FULL, msq, 0);
    const float c0 = __shfl_sync(FULL, mq0, 16);
    const float c1 = __shfl_sync(FULL, mq1, 16);
    const float c2 = __shfl_sync(FULL, mq2, 16);
    const float csq = __shfl_sync(FULL, msq, 16);

    float slotD = FLT_MAX;               // clamped d2, sorted per half
    int   slotI = 0x7FFFFFFF;
    float kthA = FLT_MAX;
    float kthB = FLT_MAX;

    // Insert all set bits of bm (candidates raw[s] at index base+s) into the
    // sorted list of half `h`. Rank-16 inserts are automatic no-ops.
    #define INSERT_LOOP(bm, raw, base, h)                                     \
        while (bm) {                                                          \
            const int s = __ffs(bm) - 1;                                      \
            bm &= bm - 1;                                                     \
            const float nd = fmaxf(__shfl_sync(FULL, raw, s), 0.0f);          \
            const int ni = (base) + s;                                        \
            const unsigned le =                                               \
                __ballot_sync(FULL, (half == (h)) && (slotD <= nd));          \
            const int pos = __popc(le);                                       \
            const float upD = __shfl_up_sync(FULL, slotD, 1);                 \
            const int   upI = __shfl_up_sync(FULL, slotI, 1);                 \
            if (half == (h)) {                                                \
                if (hl == pos)      { slotD = nd;  slotI = ni;  }             \
                else if (hl > pos)  { slotD = upD; slotI = upI; }             \
            }                                                                 \
        }

    const float4* p = pref + lane;
    #pragma unroll 2
    for (int j = 0; j < NREF / 64; ++j, p += 64) {
        const int base = j << 6;
        const float4 r0 = __ldg(p);
        const float4 r1 = __ldg(p + 32);

        const float rA0 = rawd2(a0, a1, a2, asq, r0);
        const float rA1 = rawd2(a0, a1, a2, asq, r1);
        const float rB0 = rawd2(c0, c1, c2, csq, r0);
        const float rB1 = rawd2(c0, c1, c2, csq, r1);

        unsigned mA0 = __ballot_sync(FULL, rA0 < kthA);
        unsigned mA1 = __ballot_sync(FULL, rA1 < kthA);
        unsigned mB0 = __ballot_sync(FULL, rB0 < kthB);
        unsigned mB1 = __ballot_sync(FULL, rB1 < kthB);

        if (mA0 | mA1) {
            INSERT_LOOP(mA0, rA0, base, 0)
            INSERT_LOOP(mA1, rA1, base + 32, 0)
            kthA = __shfl_sync(FULL, slotD, 15);
        }
        if (mB0 | mB1) {
            INSERT_LOOP(mB0, rB0, base, 1)
            INSERT_LOOP(mB1, rB1, base + 32, 1)
            kthB = __shfl_sync(FULL, slotD, 31);
        }
    }
    #undef INSERT_LOOP

    out_dist[gmy * KNN + hl] = __fsqrt_rn(slotD);
    out_idx [gmy * KNN + hl] = (float)slotI;
}

// ---------------------------------------------------------------------------
// kernel_launch: inputs per metadata order: ref [B,N,3] f32, query [B,M,3] f32,
// k (ignored; compile-time 16). Output: dist [B,M,16] f32 then idx [B,M,16].
// ---------------------------------------------------------------------------
extern "C" void kernel_launch(void* const* d_in, const int* in_sizes, int n_in,
                              void* d_out, int out_size) {
    const float* ref   = (const float*)d_in[0];
    const float* query = (const float*)d_in[1];
    float* out = (float*)d_out;

    knn_pack_kernel<<<(BATCH * NREF + 255) / 256, 256>>>(ref);

    const int nq = BATCH * MQ;                     // 32768 queries
    const int npairs = nq / 2;                     // 16384 warps
    knn_topk_kernel<<<npairs / WARPS_PER_BLOCK, WARPS_PER_BLOCK * 32>>>(
        query, out, out + (size_t)nq * KNN);
}